// round 2
// baseline (speedup 1.0000x reference)
#include <cuda_runtime.h>

// Problem constants
#define B_TOT   16384
#define H_DIM   128
#define T_STEPS 40
#define WPAD    132   // padded row stride for w_rec^T in smem (floats)

// Dynamic smem: sWT[128][WPAD]  (sWT[j*WPAD+h] = w_rec[h][j]),  sWin[8][128]
#define SMEM_FLOATS (H_DIM * WPAD + 8 * H_DIM)
#define SMEM_BYTES  (SMEM_FLOATS * 4)

__global__ __launch_bounds__(512) void snn_policy_kernel(
    const float* __restrict__ x,        // (B, 4)
    const float* __restrict__ w_in,     // (128, 8)
    const float* __restrict__ w_rec,    // (128, 128)
    const float* __restrict__ w_out,    // (2, 128)
    const float* __restrict__ mask,     // (T, B, 128)
    float* __restrict__ out)            // (B, 2)
{
    extern __shared__ float smem[];
    float* sWT  = smem;                   // transposed w_rec, padded
    float* sWin = smem + H_DIM * WPAD;    // transposed w_in

    const int tid = threadIdx.x;

    // Load w_rec transposed: sWT[j][h] = w_rec[h][j]. Global reads coalesced.
    for (int idx = tid; idx < H_DIM * H_DIM; idx += blockDim.x) {
        int h = idx >> 7;
        int j = idx & 127;
        sWT[j * WPAD + h] = w_rec[idx];
    }
    // Load w_in transposed: sWin[k][h] = w_in[h][k]
    for (int idx = tid; idx < 8 * H_DIM; idx += blockDim.x) {
        int h = idx >> 3;
        int k = idx & 7;
        sWin[k * H_DIM + h] = w_in[idx];
    }
    __syncthreads();

    const int lane = tid & 31;
    const int b = blockIdx.x * (blockDim.x >> 5) + (tid >> 5);  // grid covers B exactly
    const int h0 = lane << 2;   // this lane owns h0..h0+3

    // Readout weights for my 4 neurons (registers)
    float wo0[4], wo1[4];
#pragma unroll
    for (int k = 0; k < 4; k++) {
        wo0[k] = w_out[h0 + k];
        wo1[k] = w_out[H_DIM + h0 + k];
    }

    // Encoder constant currents: lanes 0-3 -> relu(50*x), lanes 4-7 -> relu(-50*x)
    float enc_c = 0.f;
    if (lane < 8) {
        float xv = x[b * 4 + (lane & 3)];
        float s  = (lane < 4) ? 50.f * xv : -50.f * xv;
        enc_c = fmaxf(s, 0.f);
    }
    float enc_v = 0.f;

    // Hidden state (4 neurons per lane)
    float v0 = 0.f, v1 = 0.f, v2 = 0.f, v3 = 0.f;   // membrane
    float c0 = 0.f, c1 = 0.f, c2 = 0.f, c3 = 0.f;   // synaptic current
    // Previous-step spike ballots: bit `lane` of zwK <-> neuron h = 4*lane + K
    unsigned zw0 = 0u, zw1 = 0u, zw2 = 0u, zw3 = 0u;
    // LI readout state (replicated across lanes, identical by construction)
    float vo0 = 0.f, vo1 = 0.f, io0 = 0.f, io1 = 0.f;
    float m0 = -1e30f, m1 = -1e30f;

    const float* mrow = mask + (size_t)b * H_DIM;
    const size_t mstep = (size_t)B_TOT * H_DIM;

    for (int t = 0; t < T_STEPS; t++) {
        // ---- encoder step (lanes 0-7 meaningful; others stay at 0) ----
        float ev = enc_v + 0.1f * (enc_c - enc_v);
        bool es = ev > 1.f;
        unsigned xs = __ballot_sync(0xffffffffu, es);
        enc_v = es ? 0.f : ev;

        // ---- hidden LIF membrane / spike / reset / current decay ----
        float vd0 = v0 + 0.1f * (c0 - v0);
        float vd1 = v1 + 0.1f * (c1 - v1);
        float vd2 = v2 + 0.1f * (c2 - v2);
        float vd3 = v3 + 0.1f * (c3 - v3);
        bool z0 = vd0 > 1.f, z1 = vd1 > 1.f, z2 = vd2 > 1.f, z3 = vd3 > 1.f;
        v0 = z0 ? 0.f : vd0;
        v1 = z1 ? 0.f : vd1;
        v2 = z2 ? 0.f : vd2;
        v3 = z3 ? 0.f : vd3;
        c0 *= 0.8f; c1 *= 0.8f; c2 *= 0.8f; c3 *= 0.8f;
        unsigned zn0 = __ballot_sync(0xffffffffu, z0);
        unsigned zn1 = __ballot_sync(0xffffffffu, z1);
        unsigned zn2 = __ballot_sync(0xffffffffu, z2);
        unsigned zn3 = __ballot_sync(0xffffffffu, z3);

        // ---- drive: i_new = i_dec + xt @ w_in^T + z_old @ w_rec^T ----
        float a0 = 0.f, a1 = 0.f, a2 = 0.f, a3 = 0.f;
        unsigned xm = xs;
        while (xm) {
            int kk = __ffs(xm) - 1; xm &= xm - 1;
            const float4 w = *(const float4*)&sWin[kk * H_DIM + h0];
            a0 += w.x; a1 += w.y; a2 += w.z; a3 += w.w;
        }
        unsigned mw;
        mw = zw0;
        while (mw) {
            int l = __ffs(mw) - 1; mw &= mw - 1;
            const float4 w = *(const float4*)&sWT[(l * 4 + 0) * WPAD + h0];
            a0 += w.x; a1 += w.y; a2 += w.z; a3 += w.w;
        }
        mw = zw1;
        while (mw) {
            int l = __ffs(mw) - 1; mw &= mw - 1;
            const float4 w = *(const float4*)&sWT[(l * 4 + 1) * WPAD + h0];
            a0 += w.x; a1 += w.y; a2 += w.z; a3 += w.w;
        }
        mw = zw2;
        while (mw) {
            int l = __ffs(mw) - 1; mw &= mw - 1;
            const float4 w = *(const float4*)&sWT[(l * 4 + 2) * WPAD + h0];
            a0 += w.x; a1 += w.y; a2 += w.z; a3 += w.w;
        }
        mw = zw3;
        while (mw) {
            int l = __ffs(mw) - 1; mw &= mw - 1;
            const float4 w = *(const float4*)&sWT[(l * 4 + 3) * WPAD + h0];
            a0 += w.x; a1 += w.y; a2 += w.z; a3 += w.w;
        }
        c0 += a0; c1 += a1; c2 += a2; c3 += a3;

        // ---- dropout + readout partial: p_o = sum_h z_new*mask*w_out[o][h] ----
        float p0 = 0.f, p1 = 0.f;
        unsigned nib = ((zn0 >> lane) & 1u)
                     | (((zn1 >> lane) & 1u) << 1)
                     | (((zn2 >> lane) & 1u) << 2)
                     | (((zn3 >> lane) & 1u) << 3);
        if (nib) {
            const float4 mv = *(const float4*)&mrow[h0];  // conditional HBM read
            if (nib & 1u) { p0 += mv.x * wo0[0]; p1 += mv.x * wo1[0]; }
            if (nib & 2u) { p0 += mv.y * wo0[1]; p1 += mv.y * wo1[1]; }
            if (nib & 4u) { p0 += mv.z * wo0[2]; p1 += mv.z * wo1[2]; }
            if (nib & 8u) { p0 += mv.w * wo0[3]; p1 += mv.w * wo1[3]; }
        }
#pragma unroll
        for (int off = 16; off > 0; off >>= 1) {
            p0 += __shfl_xor_sync(0xffffffffu, p0, off);
            p1 += __shfl_xor_sync(0xffffffffu, p1, off);
        }

        // ---- LI readout (note: vo_new uses old io; io_new uses old io) ----
        float von0 = vo0 + 0.1f * (io0 - vo0);
        float von1 = vo1 + 0.1f * (io1 - vo1);
        io0 = io0 * 0.8f + p0;
        io1 = io1 * 0.8f + p1;
        vo0 = von0; vo1 = von1;
        m0 = fmaxf(m0, von0);
        m1 = fmaxf(m1, von1);

        // carry spikes
        zw0 = zn0; zw1 = zn1; zw2 = zn2; zw3 = zn3;
        mrow += mstep;
    }

    // ---- softmax over 2 outputs ----
    if (lane == 0) {
        float mx = fmaxf(m0, m1);
        float e0 = expf(m0 - mx);
        float e1 = expf(m1 - mx);
        float s  = e0 + e1;
        out[b * 2 + 0] = e0 / s;
        out[b * 2 + 1] = e1 / s;
    }
}

extern "C" void kernel_launch(void* const* d_in, const int* in_sizes, int n_in,
                              void* d_out, int out_size)
{
    const float* x     = (const float*)d_in[0];
    const float* w_in  = (const float*)d_in[1];
    const float* w_rec = (const float*)d_in[2];
    const float* w_out = (const float*)d_in[3];
    const float* mask  = (const float*)d_in[4];
    float* out = (float*)d_out;

    cudaFuncSetAttribute(snn_policy_kernel,
                         cudaFuncAttributeMaxDynamicSharedMemorySize, SMEM_BYTES);

    // 512 threads = 16 warps = 16 batch elements per CTA; 1024 CTAs cover B=16384
    snn_policy_kernel<<<B_TOT / 16, 512, SMEM_BYTES>>>(x, w_in, w_rec, w_out, mask, out);
}